// round 9
// baseline (speedup 1.0000x reference)
#include <cuda_runtime.h>
#include <cuda_bf16.h>
#include <cstdint>
#include <cstddef>
#include <math.h>

#define H2d 4
#define Bsz 16
#define Cc 64
#define Nn 64
#define Dd 512
#define Ll (Nn*Cc)            // 4096
#define M3 (3*Dd)             // 1536
#define LDm 68                // padded smem leading dim (floats)
#define SCALE_ATT 0.125f      // 1/sqrt(64)
#define SPD_EPSF 1e-5f

#define MROWS (Bsz*Ll)        // 65536
#define K2 1024               // stored: [hi(512) | lo(512)]
#define NCHC 8                // K chunks of 64 (all 3 phases fused per chunk)
#define BMg 128
#define BNg 128
#define APITCH 72             // bf16 units per smem row (64 + 8 pad) -> 144B pitch
#define TILE_E (128*APITCH)   // bf16 elems per tile
#define STGB (4*TILE_E*2)     // stage bytes: Ahi,Alo,Whi,Wlo = 73728
#define GSTAGES 2
#define GEMM_SMEM (GSTAGES*STGB)   // 147456

// ---------------- scratch (static device memory; no allocations) ----------------
__device__ float g_qkv[(size_t)Bsz * Ll * M3];            // (B, L, 1536) fp32
__device__ float g_attn[(size_t)Bsz * Ll * Dd];           // (B, L, 512)  fp32
__device__ __nv_bfloat16 g_abuf[(size_t)MROWS * K2];      // bf16 hi|lo activations
__device__ __nv_bfloat16 g_wbuf[(size_t)M3 * K2];         // bf16 hi|lo weights

// =================================================================
// PTX helpers (plain PTX only: cp.async + mma.sync + ldmatrix)
// =================================================================
__device__ __forceinline__ uint32_t smem_u32(const void* p) {
    uint32_t a;
    asm("{ .reg .u64 t; cvta.to.shared.u64 t, %1; cvt.u32.u64 %0, t; }" : "=r"(a) : "l"(p));
    return a;
}
#define CP_ASYNC16(dst, src) \
    asm volatile("cp.async.cg.shared.global [%0], [%1], 16;" :: "r"(dst), "l"(src))
#define CP_COMMIT() asm volatile("cp.async.commit_group;" ::: "memory")
#define CP_WAIT1()  asm volatile("cp.async.wait_group 1;" ::: "memory")

__device__ __forceinline__ void ldsm_x4(uint32_t& r0, uint32_t& r1, uint32_t& r2,
                                        uint32_t& r3, uint32_t addr) {
    asm volatile("ldmatrix.sync.aligned.m8n8.x4.shared.b16 {%0,%1,%2,%3}, [%4];"
                 : "=r"(r0), "=r"(r1), "=r"(r2), "=r"(r3) : "r"(addr));
}
__device__ __forceinline__ void mma16816(float c[4], const uint32_t a[4],
                                         uint32_t b0, uint32_t b1) {
    asm volatile(
        "mma.sync.aligned.m16n8k16.row.col.f32.bf16.bf16.f32 "
        "{%0,%1,%2,%3}, {%4,%5,%6,%7}, {%8,%9}, {%0,%1,%2,%3};"
        : "+f"(c[0]), "+f"(c[1]), "+f"(c[2]), "+f"(c[3])
        : "r"(a[0]), "r"(a[1]), "r"(a[2]), "r"(a[3]), "r"(b0), "r"(b1));
}

// =================================================================
// fp32 -> bf16 hi|lo split. dst: [rows][1024] = [hi 512 | lo 512]
// =================================================================
__global__ void conv_split(const float* __restrict__ src, __nv_bfloat16* __restrict__ dst,
                           size_t total)
{
    size_t i = (size_t)blockIdx.x * blockDim.x + threadIdx.x;
    size_t e = i * 2;
    if (e >= total) return;
    size_t m = e >> 9;          // /512
    int k = (int)(e & 511);
    float2 v = *(const float2*)(src + e);
    __nv_bfloat16 h0 = __float2bfloat16(v.x);
    __nv_bfloat16 h1 = __float2bfloat16(v.y);
    __nv_bfloat16 l0 = __float2bfloat16(v.x - __bfloat162float(h0));
    __nv_bfloat16 l1 = __float2bfloat16(v.y - __bfloat162float(h1));
    __nv_bfloat162 hh; hh.x = h0; hh.y = h1;
    __nv_bfloat162 ll; ll.x = l0; ll.y = l1;
    __nv_bfloat16* base = dst + m * K2 + k;
    *(__nv_bfloat162*)(base)       = hh;
    *(__nv_bfloat162*)(base + 512) = ll;
}

// =================================================================
// mma.sync bf16x3 GEMM: C = A @ W^T + bias.
// Fused-phase chunks: each stage holds {Ahi, Alo, Whi, Wlo} for 64 K;
// inner loop does hi*hi + lo*hi + hi*lo (24 HMMA per ks vs 12 ldsm).
// 128x128 CTA tile, 8 warps of 64x32, 2-stage cp.async, 8 chunks total.
// =================================================================
__global__ __launch_bounds__(256, 1) void gemm_mma(
    const __nv_bfloat16* __restrict__ A, const __nv_bfloat16* __restrict__ W,
    const float* __restrict__ bias, float* __restrict__ C, int Nout)
{
    extern __shared__ __nv_bfloat16 smg[];
    const int tid = threadIdx.x;
    const int wid = tid >> 5, lane = tid & 31;
    const int g = lane >> 2, tig = lane & 3;
    const int warp_m = wid >> 2, warp_n = wid & 3;     // 2 x 4 warps
    const int bc = blockIdx.x, br = blockIdx.y;

    const __nv_bfloat16* gAb = A + (size_t)(br * BMg) * K2;
    const __nv_bfloat16* gBb = W + (size_t)(bc * BNg) * K2;

    const uint32_t smb = smem_u32(smg);

    // stage s layout: [Ahi | Alo | Whi | Wlo], each 128 x APITCH bf16
    auto load_chunk = [&](int kc, int s) {
        const uint32_t base = smb + (uint32_t)(s * STGB);
        const __nv_bfloat16* gA = gAb + kc * 64;
        const __nv_bfloat16* gW = gBb + kc * 64;
#pragma unroll
        for (int i = 0; i < 4; i++) {       // per tile: 128 rows x 8 x 16B
            int idx = i * 256 + tid;
            int r = idx >> 3, c16 = idx & 7;
            uint32_t dst = base + r * (APITCH * 2) + c16 * 16;
            const size_t go = (size_t)r * K2 + c16 * 8;
            CP_ASYNC16(dst,                  gA + go);         // A hi
            CP_ASYNC16(dst + TILE_E * 2,     gA + go + 512);   // A lo
            CP_ASYNC16(dst + 2 * TILE_E * 2, gW + go);         // W hi
            CP_ASYNC16(dst + 3 * TILE_E * 2, gW + go + 512);   // W lo
        }
    };

    float acc[4][4][4];
#pragma unroll
    for (int mt = 0; mt < 4; mt++)
#pragma unroll
        for (int nt = 0; nt < 4; nt++)
#pragma unroll
            for (int q = 0; q < 4; q++) acc[mt][nt][q] = 0.f;

    // ldmatrix lane address components
    const int a_row = warp_m * 64 + (lane & 15);       // + mt*16
    const int a_kof = (lane >> 4) * 8;                 // + ks*16
    const int b_col = warp_n * 32 + (lane & 7) + ((lane >> 4) << 3);  // + ntp*16
    const int b_kof = ((lane >> 3) & 1) * 8;           // + ks*16

    load_chunk(0, 0); CP_COMMIT();

    for (int kc = 0; kc < NCHC; kc++) {
        if (kc + 1 < NCHC) load_chunk(kc + 1, (kc + 1) & 1);
        CP_COMMIT();
        CP_WAIT1();            // chunk kc resident
        __syncthreads();

        const uint32_t base = smb + (uint32_t)((kc & 1) * STGB);
        const uint32_t tAh = base;
        const uint32_t tAl = base + TILE_E * 2;
        const uint32_t tWh = base + 2 * TILE_E * 2;
        const uint32_t tWl = base + 3 * TILE_E * 2;

#pragma unroll
        for (int ks = 0; ks < 4; ks++) {
            const int kb = ks * 16;
            uint32_t ah[4][4], al[4][4], wh[2][4], wl[2][4];
#pragma unroll
            for (int mt = 0; mt < 4; mt++) {
                uint32_t off = (uint32_t)(((a_row + mt * 16) * APITCH) + kb + a_kof) * 2;
                ldsm_x4(ah[mt][0], ah[mt][1], ah[mt][2], ah[mt][3], tAh + off);
                ldsm_x4(al[mt][0], al[mt][1], al[mt][2], al[mt][3], tAl + off);
            }
#pragma unroll
            for (int ntp = 0; ntp < 2; ntp++) {
                uint32_t off = (uint32_t)(((b_col + ntp * 16) * APITCH) + kb + b_kof) * 2;
                ldsm_x4(wh[ntp][0], wh[ntp][1], wh[ntp][2], wh[ntp][3], tWh + off);
                ldsm_x4(wl[ntp][0], wl[ntp][1], wl[ntp][2], wl[ntp][3], tWl + off);
            }
#pragma unroll
            for (int mt = 0; mt < 4; mt++)
#pragma unroll
                for (int ntp = 0; ntp < 2; ntp++) {
                    // hi*hi
                    mma16816(acc[mt][2 * ntp],     ah[mt], wh[ntp][0], wh[ntp][1]);
                    mma16816(acc[mt][2 * ntp + 1], ah[mt], wh[ntp][2], wh[ntp][3]);
                    // lo*hi
                    mma16816(acc[mt][2 * ntp],     al[mt], wh[ntp][0], wh[ntp][1]);
                    mma16816(acc[mt][2 * ntp + 1], al[mt], wh[ntp][2], wh[ntp][3]);
                    // hi*lo
                    mma16816(acc[mt][2 * ntp],     ah[mt], wl[ntp][0], wl[ntp][1]);
                    mma16816(acc[mt][2 * ntp + 1], ah[mt], wl[ntp][2], wl[ntp][3]);
                }
        }
        __syncthreads();       // all warps done with stage before overwrite
    }

    // ---- epilogue: direct register -> global with bias ----
#pragma unroll
    for (int mt = 0; mt < 4; mt++) {
        int row0 = br * BMg + warp_m * 64 + mt * 16 + g;
#pragma unroll
        for (int nt = 0; nt < 4; nt++) {
            int col = bc * BNg + warp_n * 32 + nt * 8 + 2 * tig;
            float b0 = bias[col], b1 = bias[col + 1];
            *(float2*)(C + (size_t)row0 * Nout + col) =
                make_float2(acc[mt][nt][0] + b0, acc[mt][nt][1] + b1);
            *(float2*)(C + (size_t)(row0 + 8) * Nout + col) =
                make_float2(acc[mt][nt][2] + b0, acc[mt][nt][3] + b1);
        }
    }
}

// =================================================================
// 64x64 smem matmul helper (validated)
// =================================================================
__device__ __forceinline__ void mm64(float* __restrict__ dst,
                                     const float* __restrict__ Am,
                                     const float* __restrict__ Bm,
                                     int tx, int ty, float dscale, float diagadd)
{
    float acc[4][4] = {};
#pragma unroll 8
    for (int k = 0; k < 64; k++) {
        float4 bv = *(const float4*)(Bm + k * LDm + 4 * tx);
        float a0 = Am[(4 * ty + 0) * LDm + k];
        float a1 = Am[(4 * ty + 1) * LDm + k];
        float a2 = Am[(4 * ty + 2) * LDm + k];
        float a3 = Am[(4 * ty + 3) * LDm + k];
        acc[0][0] += a0 * bv.x; acc[0][1] += a0 * bv.y; acc[0][2] += a0 * bv.z; acc[0][3] += a0 * bv.w;
        acc[1][0] += a1 * bv.x; acc[1][1] += a1 * bv.y; acc[1][2] += a1 * bv.z; acc[1][3] += a1 * bv.w;
        acc[2][0] += a2 * bv.x; acc[2][1] += a2 * bv.y; acc[2][2] += a2 * bv.z; acc[2][3] += a2 * bv.w;
        acc[3][0] += a3 * bv.x; acc[3][1] += a3 * bv.y; acc[3][2] += a3 * bv.z; acc[3][3] += a3 * bv.w;
    }
#pragma unroll
    for (int i = 0; i < 4; i++)
#pragma unroll
        for (int j = 0; j < 4; j++) {
            int r = 4 * ty + i, c = 4 * tx + j;
            dst[r * LDm + c] = acc[i][j] * dscale + ((r == c) ? diagadd : 0.f);
        }
    __syncthreads();
}

__device__ __forceinline__ void softmax_rows(float acc[4][4])
{
#pragma unroll
    for (int i = 0; i < 4; i++) {
        float m = fmaxf(fmaxf(acc[i][0], acc[i][1]), fmaxf(acc[i][2], acc[i][3]));
#pragma unroll
        for (int off = 8; off > 0; off >>= 1)
            m = fmaxf(m, __shfl_xor_sync(0xffffffffu, m, off, 16));
        float s = 0.f;
#pragma unroll
        for (int j = 0; j < 4; j++) { acc[i][j] = __expf(acc[i][j] - m); s += acc[i][j]; }
#pragma unroll
        for (int off = 8; off > 0; off >>= 1)
            s += __shfl_xor_sync(0xffffffffu, s, off, 16);
        float inv = 1.f / s;
#pragma unroll
        for (int j = 0; j < 4; j++) acc[i][j] *= inv;
    }
}

// =================================================================
// Temporal attention (unchanged, validated)
// =================================================================
__global__ __launch_bounds__(256, 2) void temporal_attn()
{
    extern __shared__ float smT[];
    float* Q  = smT;
    float* Kt = Q  + 64 * LDm;
    float* V  = Kt + 64 * LDm;
    float* P  = V  + 64 * LDm;
    const int tid = threadIdx.x, tx = tid & 15, ty = tid >> 4;
    const int h = blockIdx.x & 3;
    const int c = (blockIdx.x >> 2) & 63;
    const int b = blockIdx.x >> 8;

    const float* qk = g_qkv + (size_t)b * Ll * M3 + h * 64;
#pragma unroll
    for (int it = 0; it < 16; it++) {
        int idx = it * 256 + tid;
        int nn = idx >> 6, e = idx & 63;
        const float* p = qk + (size_t)(nn * Cc + c) * M3 + e;
        Q [nn * LDm + e]  = p[0];
        Kt[e  * LDm + nn] = p[Dd];
        V [nn * LDm + e]  = p[2 * Dd];
    }
    __syncthreads();

    float acc[4][4] = {};
#pragma unroll 8
    for (int k = 0; k < 64; k++) {
        float4 bv = *(const float4*)(Kt + k * LDm + 4 * tx);
        float a0 = Q[(4 * ty + 0) * LDm + k];
        float a1 = Q[(4 * ty + 1) * LDm + k];
        float a2 = Q[(4 * ty + 2) * LDm + k];
        float a3 = Q[(4 * ty + 3) * LDm + k];
        acc[0][0] += a0 * bv.x; acc[0][1] += a0 * bv.y; acc[0][2] += a0 * bv.z; acc[0][3] += a0 * bv.w;
        acc[1][0] += a1 * bv.x; acc[1][1] += a1 * bv.y; acc[1][2] += a1 * bv.z; acc[1][3] += a1 * bv.w;
        acc[2][0] += a2 * bv.x; acc[2][1] += a2 * bv.y; acc[2][2] += a2 * bv.z; acc[2][3] += a2 * bv.w;
        acc[3][0] += a3 * bv.x; acc[3][1] += a3 * bv.y; acc[3][2] += a3 * bv.z; acc[3][3] += a3 * bv.w;
    }
#pragma unroll
    for (int i = 0; i < 4; i++)
#pragma unroll
        for (int j = 0; j < 4; j++) acc[i][j] *= SCALE_ATT;

    softmax_rows(acc);

#pragma unroll
    for (int i = 0; i < 4; i++)
#pragma unroll
        for (int j = 0; j < 4; j++)
            P[(4 * ty + i) * LDm + 4 * tx + j] = acc[i][j];
    __syncthreads();

    float o[4][4] = {};
#pragma unroll 8
    for (int k = 0; k < 64; k++) {
        float4 bv = *(const float4*)(V + k * LDm + 4 * tx);
        float a0 = P[(4 * ty + 0) * LDm + k];
        float a1 = P[(4 * ty + 1) * LDm + k];
        float a2 = P[(4 * ty + 2) * LDm + k];
        float a3 = P[(4 * ty + 3) * LDm + k];
        o[0][0] += a0 * bv.x; o[0][1] += a0 * bv.y; o[0][2] += a0 * bv.z; o[0][3] += a0 * bv.w;
        o[1][0] += a1 * bv.x; o[1][1] += a1 * bv.y; o[1][2] += a1 * bv.z; o[1][3] += a1 * bv.w;
        o[2][0] += a2 * bv.x; o[2][1] += a2 * bv.y; o[2][2] += a2 * bv.z; o[2][3] += a2 * bv.w;
        o[3][0] += a3 * bv.x; o[3][1] += a3 * bv.y; o[3][2] += a3 * bv.z; o[3][3] += a3 * bv.w;
    }
#pragma unroll
    for (int i = 0; i < 4; i++) {
        size_t l = (size_t)(4 * ty + i) * Cc + c;
        *(float4*)(g_attn + ((size_t)b * Ll + l) * Dd + h * 64 + 4 * tx) =
            make_float4(o[i][0], o[i][1], o[i][2], o[i][3]);
    }
}

// =================================================================
// Spatial branch: NS 5 iters, Gregory 6 terms (validated R7)
// =================================================================
__global__ __launch_bounds__(256, 2) void spatial_riemann(
    const float* __restrict__ x, const float* __restrict__ head_scales)
{
    extern __shared__ float smS[];
    float* B0 = smS;
    float* B1 = B0 + 64 * LDm;
    float* B2 = B1 + 64 * LDm;
    float* B3 = B2 + 64 * LDm;
    float* LM = B3 + 64 * LDm;
    float* red = LM + 64 * LDm;
    __shared__ float s_alpha;

    const int tid = threadIdx.x, tx = tid & 15, ty = tid >> 4;
    const int n = blockIdx.x & 63, b = blockIdx.x >> 6;
    const float* xb = x + ((size_t)b * Ll + n * Cc) * Dd;

    float sacc[4][4] = {};
    for (int kc = 0; kc < 8; kc++) {
#pragma unroll
        for (int it = 0; it < 16; it++) {
            int idx = it * 256 + tid;
            int r = idx >> 6, col = idx & 63;
            float v = xb[(size_t)r * Dd + kc * 64 + col];
            B2[r * LDm + col] = v;
            B3[col * LDm + r] = v;
        }
        __syncthreads();
#pragma unroll 8
        for (int k = 0; k < 64; k++) {
            float4 bv = *(const float4*)(B3 + k * LDm + 4 * tx);
            float a0 = B2[(4 * ty + 0) * LDm + k];
            float a1 = B2[(4 * ty + 1) * LDm + k];
            float a2 = B2[(4 * ty + 2) * LDm + k];
            float a3 = B2[(4 * ty + 3) * LDm + k];
            sacc[0][0] += a0 * bv.x; sacc[0][1] += a0 * bv.y; sacc[0][2] += a0 * bv.z; sacc[0][3] += a0 * bv.w;
            sacc[1][0] += a1 * bv.x; sacc[1][1] += a1 * bv.y; sacc[1][2] += a1 * bv.z; sacc[1][3] += a1 * bv.w;
            sacc[2][0] += a2 * bv.x; sacc[2][1] += a2 * bv.y; sacc[2][2] += a2 * bv.z; sacc[2][3] += a2 * bv.w;
            sacc[3][0] += a3 * bv.x; sacc[3][1] += a3 * bv.y; sacc[3][2] += a3 * bv.z; sacc[3][3] += a3 * bv.w;
        }
        __syncthreads();
    }
#pragma unroll
    for (int i = 0; i < 4; i++)
#pragma unroll
        for (int j = 0; j < 4; j++) {
            int r = 4 * ty + i, c = 4 * tx + j;
            float v = sacc[i][j] * (1.f / (float)Dd);
            if (r == c) v += 1.f + SPD_EPSF;
            B0[r * LDm + c] = v;
        }
    __syncthreads();

    {
        int r = tid >> 2, seg = tid & 3;
        float s = 0.f;
#pragma unroll
        for (int j = 0; j < 16; j++) s += fabsf(B0[r * LDm + seg * 16 + j]);
        red[tid] = s;
    }
    __syncthreads();
    if (tid == 0) {
        float rmax = 0.f;
        for (int r = 0; r < 64; r++)
            rmax = fmaxf(rmax, red[4 * r] + red[4 * r + 1] + red[4 * r + 2] + red[4 * r + 3]);
        s_alpha = 2.f / (1.f + rmax);
    }
    __syncthreads();
    float alpha = s_alpha;

#pragma unroll
    for (int i = 0; i < 4; i++)
#pragma unroll
        for (int j = 0; j < 4; j++) {
            int r = 4 * ty + i, c = 4 * tx + j;
            B1[r * LDm + c] = (r == c) ? alpha : 0.f;
        }
    __syncthreads();

    for (int it = 0; it < 5; it++) {
        mm64(B2, B0, B1, tx, ty, 1.f, 0.f);
        mm64(B3, B1, B2, tx, ty, 1.f, 0.f);
#pragma unroll
        for (int i = 0; i < 4; i++)
#pragma unroll
            for (int j = 0; j < 4; j++) {
                int r = 4 * ty + i, c = 4 * tx + j;
                B1[r * LDm + c] = 2.f * B1[r * LDm + c] - B3[r * LDm + c];
            }
        __syncthreads();
    }

#pragma unroll
    for (int i = 0; i < 4; i++)
#pragma unroll
        for (int j = 0; j < 4; j++) {
            int r = 4 * ty + i, c = 4 * tx + j;
            B2[r * LDm + c] = ((r == c) ? 1.f : 0.f) - 2.f * B1[r * LDm + c];
        }
    __syncthreads();

    mm64(B0, B2, B2, tx, ty, 1.f, 0.f);   // W = Z^2

#pragma unroll
    for (int i = 0; i < 4; i++)
#pragma unroll
        for (int j = 0; j < 4; j++) {
            int r = 4 * ty + i, c = 4 * tx + j;
            B3[r * LDm + c] = (r == c) ? (1.f / 11.f) : 0.f;
        }
    __syncthreads();
    {
        float* cur = B3; float* oth = B1;
        for (int m = 4; m >= 0; m--) {
            mm64(oth, cur, B0, tx, ty, 1.f, 1.f / (float)(2 * m + 1));
            float* t = cur; cur = oth; oth = t;
        }
        mm64(LM, B2, cur, tx, ty, 2.f, 0.f);   // Lm = 2 Z P
    }

    const float* qk = g_qkv + (size_t)b * Ll * M3 + H2d * 64;
    for (int h = 0; h < H2d; h++) {
        float hs = head_scales[h];
#pragma unroll
        for (int it = 0; it < 16; it++) {
            int idx = it * 256 + tid;
            int r = idx >> 6, e = idx & 63;
            const float* p = qk + (size_t)(n * Cc + r) * M3 + h * 64 + e;
            B0[r * LDm + e] = p[0];
            B2[e * LDm + r] = p[Dd];
            B3[r * LDm + e] = p[2 * Dd];
        }
        __syncthreads();

        float a4[4][4] = {};
#pragma unroll 8
        for (int k = 0; k < 64; k++) {
            float4 bv = *(const float4*)(B2 + k * LDm + 4 * tx);
            float a0 = B0[(4 * ty + 0) * LDm + k];
            float a1 = B0[(4 * ty + 1) * LDm + k];
            float a2 = B0[(4 * ty + 2) * LDm + k];
            float a3 = B0[(4 * ty + 3) * LDm + k];
            a4[0][0] += a0 * bv.x; a4[0][1] += a0 * bv.y; a4[0][2] += a0 * bv.z; a4[0][3] += a0 * bv.w;
            a4[1][0] += a1 * bv.x; a4[1][1] += a1 * bv.y; a4[1][2] += a1 * bv.z; a4[1][3] += a1 * bv.w;
            a4[2][0] += a2 * bv.x; a4[2][1] += a2 * bv.y; a4[2][2] += a2 * bv.z; a4[2][3] += a2 * bv.w;
            a4[3][0] += a3 * bv.x; a4[3][1] += a3 * bv.y; a4[3][2] += a3 * bv.z; a4[3][3] += a3 * bv.w;
        }
#pragma unroll
        for (int i = 0; i < 4; i++)
#pragma unroll
            for (int j = 0; j < 4; j++)
                a4[i][j] = a4[i][j] * SCALE_ATT + hs * LM[(4 * ty + i) * LDm + 4 * tx + j];

        softmax_rows(a4);

#pragma unroll
        for (int i = 0; i < 4; i++)
#pragma unroll
            for (int j = 0; j < 4; j++)
                B1[(4 * ty + i) * LDm + 4 * tx + j] = a4[i][j];
        __syncthreads();

        float o[4][4] = {};
#pragma unroll 8
        for (int k = 0; k < 64; k++) {
            float4 bv = *(const float4*)(B3 + k * LDm + 4 * tx);
            float a0 = B1[(4 * ty + 0) * LDm + k];
            float a1 = B1[(4 * ty + 1) * LDm + k];
            float a2 = B1[(4 * ty + 2) * LDm + k];
            float a3 = B1[(4 * ty + 3) * LDm + k];
            o[0][0] += a0 * bv.x; o[0][1] += a0 * bv.y; o[0][2] += a0 * bv.z; o[0][3] += a0 * bv.w;
            o[1][0] += a1 * bv.x; o[1][1] += a1 * bv.y; o[1][2] += a1 * bv.z; o[1][3] += a1 * bv.w;
            o[2][0] += a2 * bv.x; o[2][1] += a2 * bv.y; o[2][2] += a2 * bv.z; o[2][3] += a2 * bv.w;
            o[3][0] += a3 * bv.x; o[3][1] += a3 * bv.y; o[3][2] += a3 * bv.z; o[3][3] += a3 * bv.w;
        }
#pragma unroll
        for (int i = 0; i < 4; i++) {
            size_t l = (size_t)n * Cc + 4 * ty + i;
            *(float4*)(g_attn + ((size_t)b * Ll + l) * Dd + (H2d + h) * 64 + 4 * tx) =
                make_float4(o[i][0], o[i][1], o[i][2], o[i][3]);
        }
        __syncthreads();
    }
}

// =================================================================
// launch
// =================================================================
extern "C" void kernel_launch(void* const* d_in, const int* in_sizes, int n_in,
                              void* d_out, int out_size)
{
    const float* x     = (const float*)d_in[0];
    const float* qkv_w = (const float*)d_in[1];
    const float* qkv_b = (const float*)d_in[2];
    const float* fc_w  = (const float*)d_in[3];
    const float* fc_b  = (const float*)d_in[4];
    const float* hsc   = (const float*)d_in[5];
    float* out = (float*)d_out;

    float* p_qkv = nullptr;
    float* p_attn = nullptr;
    __nv_bfloat16* p_abuf = nullptr;
    __nv_bfloat16* p_wbuf = nullptr;
    cudaGetSymbolAddress((void**)&p_qkv, g_qkv);
    cudaGetSymbolAddress((void**)&p_attn, g_attn);
    cudaGetSymbolAddress((void**)&p_abuf, g_abuf);
    cudaGetSymbolAddress((void**)&p_wbuf, g_wbuf);

    const int smemT = 4 * 64 * LDm * (int)sizeof(float);
    const int smemS = 5 * 64 * LDm * (int)sizeof(float) + 256 * 4;
    cudaFuncSetAttribute(temporal_attn, cudaFuncAttributeMaxDynamicSharedMemorySize, smemT);
    cudaFuncSetAttribute(spatial_riemann, cudaFuncAttributeMaxDynamicSharedMemorySize, smemS);
    cudaFuncSetAttribute(gemm_mma, cudaFuncAttributeMaxDynamicSharedMemorySize, GEMM_SMEM);

    // 1) split x and qkv_w to bf16 hi|lo
    {
        size_t tot = (size_t)MROWS * Dd;
        conv_split<<<(unsigned)(tot / 512), 256>>>(x, p_abuf, tot);
        size_t totw = (size_t)M3 * Dd;
        conv_split<<<(unsigned)(totw / 512), 256>>>(qkv_w, p_wbuf, totw);
    }
    // 2) QKV projection via mma.sync bf16x3
    {
        dim3 grid(M3 / BNg, MROWS / BMg);   // (12, 512)
        gemm_mma<<<grid, 256, GEMM_SMEM>>>(p_abuf, p_wbuf, qkv_b, p_qkv, M3);
    }
    // 3) temporal heads
    temporal_attn<<<Bsz * Cc * H2d, 256, smemT>>>();
    // 4) SPD log bias + spatial heads
    spatial_riemann<<<Bsz * Nn, 256, smemS>>>(x, hsc);
    // 5) split attn output and fc_w to bf16 hi|lo
    {
        size_t tot = (size_t)MROWS * Dd;
        conv_split<<<(unsigned)(tot / 512), 256>>>(p_attn, p_abuf, tot);
        size_t totw = (size_t)Dd * Dd;
        conv_split<<<(unsigned)(totw / 512), 256>>>(fc_w, p_wbuf, totw);
    }
    // 6) output projection via mma.sync bf16x3
    {
        dim3 grid(Dd / BNg, MROWS / BMg);   // (4, 512)
        gemm_mma<<<grid, 256, GEMM_SMEM>>>(p_abuf, p_wbuf, fc_b, out, Dd);
    }
}

// round 10
// speedup vs baseline: 1.2515x; 1.2515x over previous
#include <cuda_runtime.h>
#include <cuda_fp16.h>
#include <cstdint>
#include <cstddef>
#include <math.h>

#define H2d 4
#define Bsz 16
#define Cc 64
#define Nn 64
#define Dd 512
#define Ll (Nn*Cc)            // 4096
#define M3 (3*Dd)             // 1536
#define LDm 68                // padded smem leading dim (floats)
#define SCALE_ATT 0.125f      // 1/sqrt(64)
#define SPD_EPSF 1e-5f

#define MROWS (Bsz*Ll)        // 65536
#define K2 1024               // stored: [hi(512) | lo(512)] fp16
#define BK 64                 // fp16 K per chunk
#define NCH 16                // compute chunks: 2 phases x 8 chunks of 64
#define BMg 128
#define BNg 128
#define APITCH 72             // fp16 units per smem row (64 + 8 pad) -> 144B pitch
#define STG_TILE (128*APITCH) // fp16 elems per tile per stage
#define STAGES 3

// ---------------- scratch (static device memory; no allocations) ----------------
__device__ float g_qkv[(size_t)Bsz * Ll * M3];            // (B, L, 1536) fp32
__device__ float g_attn[(size_t)Bsz * Ll * Dd];           // (B, L, 512)  fp32
__device__ __half g_abuf[(size_t)MROWS * K2];             // fp16 hi|lo activations
__device__ __half g_wbuf[(size_t)M3 * K2];                // fp16 hi|lo weights

// =================================================================
// PTX helpers (plain PTX only: cp.async + mma.sync + ldmatrix)
// =================================================================
__device__ __forceinline__ uint32_t smem_u32(const void* p) {
    uint32_t a;
    asm("{ .reg .u64 t; cvta.to.shared.u64 t, %1; cvt.u32.u64 %0, t; }" : "=r"(a) : "l"(p));
    return a;
}
#define CP_ASYNC16(dst, src) \
    asm volatile("cp.async.cg.shared.global [%0], [%1], 16;" :: "r"(dst), "l"(src))
#define CP_COMMIT() asm volatile("cp.async.commit_group;" ::: "memory")
#define CP_WAIT1()  asm volatile("cp.async.wait_group 1;" ::: "memory")

__device__ __forceinline__ void ldsm_x4(uint32_t& r0, uint32_t& r1, uint32_t& r2,
                                        uint32_t& r3, uint32_t addr) {
    asm volatile("ldmatrix.sync.aligned.m8n8.x4.shared.b16 {%0,%1,%2,%3}, [%4];"
                 : "=r"(r0), "=r"(r1), "=r"(r2), "=r"(r3) : "r"(addr));
}
__device__ __forceinline__ void mma16816(float c[4], uint32_t a0, uint32_t a1,
                                         uint32_t a2, uint32_t a3,
                                         uint32_t b0, uint32_t b1) {
    asm volatile(
        "mma.sync.aligned.m16n8k16.row.col.f32.f16.f16.f32 "
        "{%0,%1,%2,%3}, {%4,%5,%6,%7}, {%8,%9}, {%0,%1,%2,%3};"
        : "+f"(c[0]), "+f"(c[1]), "+f"(c[2]), "+f"(c[3])
        : "r"(a0), "r"(a1), "r"(a2), "r"(a3), "r"(b0), "r"(b1));
}

// =================================================================
// fp32 -> fp16 hi|lo split. dst: [rows][1024] = [hi 512 | lo 512]
// =================================================================
__global__ void conv_split(const float* __restrict__ src, __half* __restrict__ dst,
                           size_t total)
{
    size_t i = (size_t)blockIdx.x * blockDim.x + threadIdx.x;
    size_t e = i * 2;
    if (e >= total) return;
    size_t m = e >> 9;          // /512
    int k = (int)(e & 511);
    float2 v = *(const float2*)(src + e);
    __half h0 = __float2half(v.x);
    __half h1 = __float2half(v.y);
    __half l0 = __float2half(v.x - __half2float(h0));
    __half l1 = __float2half(v.y - __half2float(h1));
    __half2 hh; hh.x = h0; hh.y = h1;
    __half2 ll; ll.x = l0; ll.y = l1;
    __half* base = dst + m * K2 + k;
    *(__half2*)(base)       = hh;
    *(__half2*)(base + 512) = ll;
}

// =================================================================
// mma.sync fp16x2 GEMM: C = A @ W^T + bias.
// 2 K-phases over [hi|lo] storage: hi_A*hi_W + lo_A*hi_W = A*hi_W;
// residual A*lo_W ~ eps_fp16 ~ 2-3e-4 relative (within 1e-3 gate).
// 128x128 CTA tile, 8 warps of 64x32, BK=64, 3-stage cp.async, ldmatrix.
// =================================================================
__global__ __launch_bounds__(256, 2) void gemm_mma(
    const __half* __restrict__ A, const __half* __restrict__ W,
    const float* __restrict__ bias, float* __restrict__ C, int Nout)
{
    extern __shared__ __half smg[];
    const int tid = threadIdx.x;
    const int wid = tid >> 5, lane = tid & 31;
    const int g = lane >> 2, tig = lane & 3;
    const int warp_m = wid >> 2, warp_n = wid & 3;     // 2 x 4 warps
    const int bc = blockIdx.x, br = blockIdx.y;

    const __half* gAb = A + (size_t)(br * BMg) * K2;
    const __half* gBb = W + (size_t)(bc * BNg) * K2;

    const uint32_t smb = smem_u32(smg);

    // per-chunk segment offsets: phase 0: hiA*hiW, 1: loA*hiW
    auto load_chunk = [&](int kc, int s) {
        const int phase = kc >> 3, k8 = kc & 7;
        const int aoff = ((phase == 1) ? 512 : 0) + k8 * BK;
        const int boff = k8 * BK;                      // W always hi
        const uint32_t smA = smb + (uint32_t)(s * 2 * STG_TILE) * 2;
        const uint32_t smB = smA + (uint32_t)STG_TILE * 2;
        const __half* gA = gAb + aoff;
        const __half* gB = gBb + boff;
#pragma unroll
        for (int i = 0; i < 4; i++) {       // A: 128 rows x 8 x 16B
            int idx = i * 256 + tid;
            int r = idx >> 3, c16 = idx & 7;
            CP_ASYNC16(smA + r * (APITCH * 2) + c16 * 16, gA + (size_t)r * K2 + c16 * 8);
        }
#pragma unroll
        for (int i = 0; i < 4; i++) {       // B: 128 rows x 8 x 16B
            int idx = i * 256 + tid;
            int r = idx >> 3, c16 = idx & 7;
            CP_ASYNC16(smB + r * (APITCH * 2) + c16 * 16, gB + (size_t)r * K2 + c16 * 8);
        }
    };

    float acc[4][4][4];
#pragma unroll
    for (int mt = 0; mt < 4; mt++)
#pragma unroll
        for (int nt = 0; nt < 4; nt++)
#pragma unroll
            for (int q = 0; q < 4; q++) acc[mt][nt][q] = 0.f;

    // ldmatrix lane address components
    const int a_row = warp_m * 64 + (lane & 15);       // + mt*16
    const int a_kof = (lane >> 4) * 8;                 // + ks*16
    const int b_col = warp_n * 32 + (lane & 7) + ((lane >> 4) << 3);  // + ntp*16
    const int b_kof = ((lane >> 3) & 1) * 8;           // + ks*16

    load_chunk(0, 0); CP_COMMIT();
    load_chunk(1, 1); CP_COMMIT();

    for (int kc = 0; kc < NCH; kc++) {
        CP_WAIT1();            // chunk kc resident
        __syncthreads();
        if (kc + 2 < NCH) load_chunk(kc + 2, (kc + 2) % STAGES);
        CP_COMMIT();

        const int s = kc % STAGES;
        const uint32_t smA = smb + (uint32_t)(s * 2 * STG_TILE) * 2;
        const uint32_t smB = smA + (uint32_t)STG_TILE * 2;

#pragma unroll
        for (int ks = 0; ks < 4; ks++) {
            const int kb = ks * 16;
            uint32_t af[4][4], bf[2][4];
#pragma unroll
            for (int mt = 0; mt < 4; mt++) {
                uint32_t addr = smA + (uint32_t)(((a_row + mt * 16) * APITCH) + kb + a_kof) * 2;
                ldsm_x4(af[mt][0], af[mt][1], af[mt][2], af[mt][3], addr);
            }
#pragma unroll
            for (int ntp = 0; ntp < 2; ntp++) {
                uint32_t addr = smB + (uint32_t)(((b_col + ntp * 16) * APITCH) + kb + b_kof) * 2;
                ldsm_x4(bf[ntp][0], bf[ntp][1], bf[ntp][2], bf[ntp][3], addr);
            }
#pragma unroll
            for (int mt = 0; mt < 4; mt++)
#pragma unroll
                for (int ntp = 0; ntp < 2; ntp++) {
                    mma16816(acc[mt][2 * ntp],     af[mt][0], af[mt][1], af[mt][2], af[mt][3],
                             bf[ntp][0], bf[ntp][1]);
                    mma16816(acc[mt][2 * ntp + 1], af[mt][0], af[mt][1], af[mt][2], af[mt][3],
                             bf[ntp][2], bf[ntp][3]);
                }
        }
    }

    // ---- epilogue: direct register -> global with bias ----
#pragma unroll
    for (int mt = 0; mt < 4; mt++) {
        int row0 = br * BMg + warp_m * 64 + mt * 16 + g;
#pragma unroll
        for (int nt = 0; nt < 4; nt++) {
            int col = bc * BNg + warp_n * 32 + nt * 8 + 2 * tig;
            float b0 = bias[col], b1 = bias[col + 1];
            *(float2*)(C + (size_t)row0 * Nout + col) =
                make_float2(acc[mt][nt][0] + b0, acc[mt][nt][1] + b1);
            *(float2*)(C + (size_t)(row0 + 8) * Nout + col) =
                make_float2(acc[mt][nt][2] + b0, acc[mt][nt][3] + b1);
        }
    }
}

// =================================================================
// 64x64 smem matmul helper (validated)
// =================================================================
__device__ __forceinline__ void mm64(float* __restrict__ dst,
                                     const float* __restrict__ Am,
                                     const float* __restrict__ Bm,
                                     int tx, int ty, float dscale, float diagadd)
{
    float acc[4][4] = {};
#pragma unroll 8
    for (int k = 0; k < 64; k++) {
        float4 bv = *(const float4*)(Bm + k * LDm + 4 * tx);
        float a0 = Am[(4 * ty + 0) * LDm + k];
        float a1 = Am[(4 * ty + 1) * LDm + k];
        float a2 = Am[(4 * ty + 2) * LDm + k];
        float a3 = Am[(4 * ty + 3) * LDm + k];
        acc[0][0] += a0 * bv.x; acc[0][1] += a0 * bv.y; acc[0][2] += a0 * bv.z; acc[0][3] += a0 * bv.w;
        acc[1][0] += a1 * bv.x; acc[1][1] += a1 * bv.y; acc[1][2] += a1 * bv.z; acc[1][3] += a1 * bv.w;
        acc[2][0] += a2 * bv.x; acc[2][1] += a2 * bv.y; acc[2][2] += a2 * bv.z; acc[2][3] += a2 * bv.w;
        acc[3][0] += a3 * bv.x; acc[3][1] += a3 * bv.y; acc[3][2] += a3 * bv.z; acc[3][3] += a3 * bv.w;
    }
#pragma unroll
    for (int i = 0; i < 4; i++)
#pragma unroll
        for (int j = 0; j < 4; j++) {
            int r = 4 * ty + i, c = 4 * tx + j;
            dst[r * LDm + c] = acc[i][j] * dscale + ((r == c) ? diagadd : 0.f);
        }
    __syncthreads();
}

__device__ __forceinline__ void softmax_rows(float acc[4][4])
{
#pragma unroll
    for (int i = 0; i < 4; i++) {
        float m = fmaxf(fmaxf(acc[i][0], acc[i][1]), fmaxf(acc[i][2], acc[i][3]));
#pragma unroll
        for (int off = 8; off > 0; off >>= 1)
            m = fmaxf(m, __shfl_xor_sync(0xffffffffu, m, off, 16));
        float s = 0.f;
#pragma unroll
        for (int j = 0; j < 4; j++) { acc[i][j] = __expf(acc[i][j] - m); s += acc[i][j]; }
#pragma unroll
        for (int off = 8; off > 0; off >>= 1)
            s += __shfl_xor_sync(0xffffffffu, s, off, 16);
        float inv = 1.f / s;
#pragma unroll
        for (int j = 0; j < 4; j++) acc[i][j] *= inv;
    }
}

// =================================================================
// Temporal attention (unchanged, validated)
// =================================================================
__global__ __launch_bounds__(256, 2) void temporal_attn()
{
    extern __shared__ float smT[];
    float* Q  = smT;
    float* Kt = Q  + 64 * LDm;
    float* V  = Kt + 64 * LDm;
    float* P  = V  + 64 * LDm;
    const int tid = threadIdx.x, tx = tid & 15, ty = tid >> 4;
    const int h = blockIdx.x & 3;
    const int c = (blockIdx.x >> 2) & 63;
    const int b = blockIdx.x >> 8;

    const float* qk = g_qkv + (size_t)b * Ll * M3 + h * 64;
#pragma unroll
    for (int it = 0; it < 16; it++) {
        int idx = it * 256 + tid;
        int nn = idx >> 6, e = idx & 63;
        const float* p = qk + (size_t)(nn * Cc + c) * M3 + e;
        Q [nn * LDm + e]  = p[0];
        Kt[e  * LDm + nn] = p[Dd];
        V [nn * LDm + e]  = p[2 * Dd];
    }
    __syncthreads();

    float acc[4][4] = {};
#pragma unroll 8
    for (int k = 0; k < 64; k++) {
        float4 bv = *(const float4*)(Kt + k * LDm + 4 * tx);
        float a0 = Q[(4 * ty + 0) * LDm + k];
        float a1 = Q[(4 * ty + 1) * LDm + k];
        float a2 = Q[(4 * ty + 2) * LDm + k];
        float a3 = Q[(4 * ty + 3) * LDm + k];
        acc[0][0] += a0 * bv.x; acc[0][1] += a0 * bv.y; acc[0][2] += a0 * bv.z; acc[0][3] += a0 * bv.w;
        acc[1][0] += a1 * bv.x; acc[1][1] += a1 * bv.y; acc[1][2] += a1 * bv.z; acc[1][3] += a1 * bv.w;
        acc[2][0] += a2 * bv.x; acc[2][1] += a2 * bv.y; acc[2][2] += a2 * bv.z; acc[2][3] += a2 * bv.w;
        acc[3][0] += a3 * bv.x; acc[3][1] += a3 * bv.y; acc[3][2] += a3 * bv.z; acc[3][3] += a3 * bv.w;
    }
#pragma unroll
    for (int i = 0; i < 4; i++)
#pragma unroll
        for (int j = 0; j < 4; j++) acc[i][j] *= SCALE_ATT;

    softmax_rows(acc);

#pragma unroll
    for (int i = 0; i < 4; i++)
#pragma unroll
        for (int j = 0; j < 4; j++)
            P[(4 * ty + i) * LDm + 4 * tx + j] = acc[i][j];
    __syncthreads();

    float o[4][4] = {};
#pragma unroll 8
    for (int k = 0; k < 64; k++) {
        float4 bv = *(const float4*)(V + k * LDm + 4 * tx);
        float a0 = P[(4 * ty + 0) * LDm + k];
        float a1 = P[(4 * ty + 1) * LDm + k];
        float a2 = P[(4 * ty + 2) * LDm + k];
        float a3 = P[(4 * ty + 3) * LDm + k];
        o[0][0] += a0 * bv.x; o[0][1] += a0 * bv.y; o[0][2] += a0 * bv.z; o[0][3] += a0 * bv.w;
        o[1][0] += a1 * bv.x; o[1][1] += a1 * bv.y; o[1][2] += a1 * bv.z; o[1][3] += a1 * bv.w;
        o[2][0] += a2 * bv.x; o[2][1] += a2 * bv.y; o[2][2] += a2 * bv.z; o[2][3] += a2 * bv.w;
        o[3][0] += a3 * bv.x; o[3][1] += a3 * bv.y; o[3][2] += a3 * bv.z; o[3][3] += a3 * bv.w;
    }
#pragma unroll
    for (int i = 0; i < 4; i++) {
        size_t l = (size_t)(4 * ty + i) * Cc + c;
        *(float4*)(g_attn + ((size_t)b * Ll + l) * Dd + h * 64 + 4 * tx) =
            make_float4(o[i][0], o[i][1], o[i][2], o[i][3]);
    }
}

// =================================================================
// Spatial branch: NS 5 iters, Gregory 6 terms (validated R7)
// =================================================================
__global__ __launch_bounds__(256, 2) void spatial_riemann(
    const float* __restrict__ x, const float* __restrict__ head_scales)
{
    extern __shared__ float smS[];
    float* B0 = smS;
    float* B1 = B0 + 64 * LDm;
    float* B2 = B1 + 64 * LDm;
    float* B3 = B2 + 64 * LDm;
    float* LM = B3 + 64 * LDm;
    float* red = LM + 64 * LDm;
    __shared__ float s_alpha;

    const int tid = threadIdx.x, tx = tid & 15, ty = tid >> 4;
    const int n = blockIdx.x & 63, b = blockIdx.x >> 6;
    const float* xb = x + ((size_t)b * Ll + n * Cc) * Dd;

    float sacc[4][4] = {};
    for (int kc = 0; kc < 8; kc++) {
#pragma unroll
        for (int it = 0; it < 16; it++) {
            int idx = it * 256 + tid;
            int r = idx >> 6, col = idx & 63;
            float v = xb[(size_t)r * Dd + kc * 64 + col];
            B2[r * LDm + col] = v;
            B3[col * LDm + r] = v;
        }
        __syncthreads();
#pragma unroll 8
        for (int k = 0; k < 64; k++) {
            float4 bv = *(const float4*)(B3 + k * LDm + 4 * tx);
            float a0 = B2[(4 * ty + 0) * LDm + k];
            float a1 = B2[(4 * ty + 1) * LDm + k];
            float a2 = B2[(4 * ty + 2) * LDm + k];
            float a3 = B2[(4 * ty + 3) * LDm + k];
            sacc[0][0] += a0 * bv.x; sacc[0][1] += a0 * bv.y; sacc[0][2] += a0 * bv.z; sacc[0][3] += a0 * bv.w;
            sacc[1][0] += a1 * bv.x; sacc[1][1] += a1 * bv.y; sacc[1][2] += a1 * bv.z; sacc[1][3] += a1 * bv.w;
            sacc[2][0] += a2 * bv.x; sacc[2][1] += a2 * bv.y; sacc[2][2] += a2 * bv.z; sacc[2][3] += a2 * bv.w;
            sacc[3][0] += a3 * bv.x; sacc[3][1] += a3 * bv.y; sacc[3][2] += a3 * bv.z; sacc[3][3] += a3 * bv.w;
        }
        __syncthreads();
    }
#pragma unroll
    for (int i = 0; i < 4; i++)
#pragma unroll
        for (int j = 0; j < 4; j++) {
            int r = 4 * ty + i, c = 4 * tx + j;
            float v = sacc[i][j] * (1.f / (float)Dd);
            if (r == c) v += 1.f + SPD_EPSF;
            B0[r * LDm + c] = v;
        }
    __syncthreads();

    {
        int r = tid >> 2, seg = tid & 3;
        float s = 0.f;
#pragma unroll
        for (int j = 0; j < 16; j++) s += fabsf(B0[r * LDm + seg * 16 + j]);
        red[tid] = s;
    }
    __syncthreads();
    if (tid == 0) {
        float rmax = 0.f;
        for (int r = 0; r < 64; r++)
            rmax = fmaxf(rmax, red[4 * r] + red[4 * r + 1] + red[4 * r + 2] + red[4 * r + 3]);
        s_alpha = 2.f / (1.f + rmax);
    }
    __syncthreads();
    float alpha = s_alpha;

#pragma unroll
    for (int i = 0; i < 4; i++)
#pragma unroll
        for (int j = 0; j < 4; j++) {
            int r = 4 * ty + i, c = 4 * tx + j;
            B1[r * LDm + c] = (r == c) ? alpha : 0.f;
        }
    __syncthreads();

    for (int it = 0; it < 5; it++) {
        mm64(B2, B0, B1, tx, ty, 1.f, 0.f);
        mm64(B3, B1, B2, tx, ty, 1.f, 0.f);
#pragma unroll
        for (int i = 0; i < 4; i++)
#pragma unroll
            for (int j = 0; j < 4; j++) {
                int r = 4 * ty + i, c = 4 * tx + j;
                B1[r * LDm + c] = 2.f * B1[r * LDm + c] - B3[r * LDm + c];
            }
        __syncthreads();
    }

#pragma unroll
    for (int i = 0; i < 4; i++)
#pragma unroll
        for (int j = 0; j < 4; j++) {
            int r = 4 * ty + i, c = 4 * tx + j;
            B2[r * LDm + c] = ((r == c) ? 1.f : 0.f) - 2.f * B1[r * LDm + c];
        }
    __syncthreads();

    mm64(B0, B2, B2, tx, ty, 1.f, 0.f);   // W = Z^2

#pragma unroll
    for (int i = 0; i < 4; i++)
#pragma unroll
        for (int j = 0; j < 4; j++) {
            int r = 4 * ty + i, c = 4 * tx + j;
            B3[r * LDm + c] = (r == c) ? (1.f / 11.f) : 0.f;
        }
    __syncthreads();
    {
        float* cur = B3; float* oth = B1;
        for (int m = 4; m >= 0; m--) {
            mm64(oth, cur, B0, tx, ty, 1.f, 1.f / (float)(2 * m + 1));
            float* t = cur; cur = oth; oth = t;
        }
        mm64(LM, B2, cur, tx, ty, 2.f, 0.f);   // Lm = 2 Z P
    }

    const float* qk = g_qkv + (size_t)b * Ll * M3 + H2d * 64;
    for (int h = 0; h < H2d; h++) {
        float hs = head_scales[h];
#pragma unroll
        for (int it = 0; it < 16; it++) {
            int idx = it * 256 + tid;
            int r = idx >> 6, e = idx & 63;
            const float* p = qk + (size_t)(n * Cc + r) * M3 + h * 64 + e;
            B0[r * LDm + e] = p[0];
            B2[e * LDm + r] = p[Dd];
            B3[r * LDm + e] = p[2 * Dd];
        }
        __syncthreads();

        float a4[4][4] = {};
#pragma unroll 8
        for (int k = 0; k < 64; k++) {
            float4 bv = *(const float4*)(B2 + k * LDm + 4 * tx);
            float a0 = B0[(4 * ty + 0) * LDm + k];
            float a1 = B0[(4 * ty + 1) * LDm + k];
            float a2 = B0[(4 * ty + 2) * LDm + k];
            float a3 = B0[(4 * ty + 3) * LDm + k];
            a4[0][0] += a0 * bv.x; a4[0][1] += a0 * bv.y; a4[0][2] += a0 * bv.z; a4[0][3] += a0 * bv.w;
            a4[1][0] += a1 * bv.x; a4[1][1] += a1 * bv.y; a4[1][2] += a1 * bv.z; a4[1][3] += a1 * bv.w;
            a4[2][0] += a2 * bv.x; a4[2][1] += a2 * bv.y; a4[2][2] += a2 * bv.z; a4[2][3] += a2 * bv.w;
            a4[3][0] += a3 * bv.x; a4[3][1] += a3 * bv.y; a4[3][2] += a3 * bv.z; a4[3][3] += a3 * bv.w;
        }
#pragma unroll
        for (int i = 0; i < 4; i++)
#pragma unroll
            for (int j = 0; j < 4; j++)
                a4[i][j] = a4[i][j] * SCALE_ATT + hs * LM[(4 * ty + i) * LDm + 4 * tx + j];

        softmax_rows(a4);

#pragma unroll
        for (int i = 0; i < 4; i++)
#pragma unroll
            for (int j = 0; j < 4; j++)
                B1[(4 * ty + i) * LDm + 4 * tx + j] = a4[i][j];
        __syncthreads();

        float o[4][4] = {};
#pragma unroll 8
        for (int k = 0; k < 64; k++) {
            float4 bv = *(const float4*)(B3 + k * LDm + 4 * tx);
            float a0 = B1[(4 * ty + 0) * LDm + k];
            float a1 = B1[(4 * ty + 1) * LDm + k];
            float a2 = B1[(4 * ty + 2) * LDm + k];
            float a3 = B1[(4 * ty + 3) * LDm + k];
            o[0][0] += a0 * bv.x; o[0][1] += a0 * bv.y; o[0][2] += a0 * bv.z; o[0][3] += a0 * bv.w;
            o[1][0] += a1 * bv.x; o[1][1] += a1 * bv.y; o[1][2] += a1 * bv.z; o[1][3] += a1 * bv.w;
            o[2][0] += a2 * bv.x; o[2][1] += a2 * bv.y; o[2][2] += a2 * bv.z; o[2][3] += a2 * bv.w;
            o[3][0] += a3 * bv.x; o[3][1] += a3 * bv.y; o[3][2] += a3 * bv.z; o[3][3] += a3 * bv.w;
        }
#pragma unroll
        for (int i = 0; i < 4; i++) {
            size_t l = (size_t)n * Cc + 4 * ty + i;
            *(float4*)(g_attn + ((size_t)b * Ll + l) * Dd + (H2d + h) * 64 + 4 * tx) =
                make_float4(o[i][0], o[i][1], o[i][2], o[i][3]);
        }
        __syncthreads();
    }
}

// =================================================================
// launch
// =================================================================
extern "C" void kernel_launch(void* const* d_in, const int* in_sizes, int n_in,
                              void* d_out, int out_size)
{
    const float* x     = (const float*)d_in[0];
    const float* qkv_w = (const float*)d_in[1];
    const float* qkv_b = (const float*)d_in[2];
    const float* fc_w  = (const float*)d_in[3];
    const float* fc_b  = (const float*)d_in[4];
    const float* hsc   = (const float*)d_in[5];
    float* out = (float*)d_out;

    float* p_qkv = nullptr;
    float* p_attn = nullptr;
    __half* p_abuf = nullptr;
    __half* p_wbuf = nullptr;
    cudaGetSymbolAddress((void**)&p_qkv, g_qkv);
    cudaGetSymbolAddress((void**)&p_attn, g_attn);
    cudaGetSymbolAddress((void**)&p_abuf, g_abuf);
    cudaGetSymbolAddress((void**)&p_wbuf, g_wbuf);

    const int smemT = 4 * 64 * LDm * (int)sizeof(float);
    const int smemS = 5 * 64 * LDm * (int)sizeof(float) + 256 * 4;
    const int smemG = STAGES * 2 * STG_TILE * (int)sizeof(__half);   // 110592
    cudaFuncSetAttribute(temporal_attn, cudaFuncAttributeMaxDynamicSharedMemorySize, smemT);
    cudaFuncSetAttribute(spatial_riemann, cudaFuncAttributeMaxDynamicSharedMemorySize, smemS);
    cudaFuncSetAttribute(gemm_mma, cudaFuncAttributeMaxDynamicSharedMemorySize, smemG);

    // 1) split x and qkv_w to fp16 hi|lo
    {
        size_t tot = (size_t)MROWS * Dd;
        conv_split<<<(unsigned)(tot / 512), 256>>>(x, p_abuf, tot);
        size_t totw = (size_t)M3 * Dd;
        conv_split<<<(unsigned)(totw / 512), 256>>>(qkv_w, p_wbuf, totw);
    }
    // 2) QKV projection via mma.sync fp16x2
    {
        dim3 grid(M3 / BNg, MROWS / BMg);   // (12, 512)
        gemm_mma<<<grid, 256, smemG>>>(p_abuf, p_wbuf, qkv_b, p_qkv, M3);
    }
    // 3) temporal heads
    temporal_attn<<<Bsz * Cc * H2d, 256, smemT>>>();
    // 4) SPD log bias + spatial heads
    spatial_riemann<<<Bsz * Nn, 256, smemS>>>(x, hsc);
    // 5) split attn output and fc_w to fp16 hi|lo
    {
        size_t tot = (size_t)MROWS * Dd;
        conv_split<<<(unsigned)(tot / 512), 256>>>(p_attn, p_abuf, tot);
        size_t totw = (size_t)Dd * Dd;
        conv_split<<<(unsigned)(totw / 512), 256>>>(fc_w, p_wbuf, totw);
    }
    // 6) output projection via mma.sync fp16x2
    {
        dim3 grid(Dd / BNg, MROWS / BMg);   // (4, 512)
        gemm_mma<<<grid, 256, smemG>>>(p_abuf, p_wbuf, fc_b, out, Dd);
    }
}

// round 11
// speedup vs baseline: 1.7357x; 1.3869x over previous
#include <cuda_runtime.h>
#include <cuda_fp16.h>
#include <cstdint>
#include <cstddef>
#include <math.h>

#define H2d 4
#define Bsz 16
#define Cc 64
#define Nn 64
#define Dd 512
#define Ll (Nn*Cc)            // 4096
#define M3 (3*Dd)             // 1536
#define LDm 68                // padded smem leading dim (floats)
#define SCALE_ATT 0.125f      // 1/sqrt(64)
#define SPD_EPSF 1e-5f

#define MROWS (Bsz*Ll)        // 65536
#define KK 512                // fp16 K (single phase)
#define BK 64                 // fp16 K per chunk
#define NCH 8                 // chunks of 64
#define BMg 128
#define BNg 128
#define APITCH 72             // fp16 units per smem row (64 + 8 pad) -> 144B pitch
#define STG_TILE (128*APITCH) // fp16 elems per tile per stage
#define STAGES 3

// ---------------- scratch (static device memory; no allocations) ----------------
__device__ float g_qkv[(size_t)Bsz * Ll * M3];            // (B, L, 1536) fp32
__device__ __half g_abuf[(size_t)MROWS * KK];             // fp16 activations (x, then attn out)
__device__ __half g_wbuf[(size_t)M3 * KK];                // fp16 weights

// =================================================================
// PTX helpers (plain PTX only: cp.async + mma.sync + ldmatrix)
// =================================================================
__device__ __forceinline__ uint32_t smem_u32(const void* p) {
    uint32_t a;
    asm("{ .reg .u64 t; cvta.to.shared.u64 t, %1; cvt.u32.u64 %0, t; }" : "=r"(a) : "l"(p));
    return a;
}
#define CP_ASYNC16(dst, src) \
    asm volatile("cp.async.cg.shared.global [%0], [%1], 16;" :: "r"(dst), "l"(src))
#define CP_COMMIT() asm volatile("cp.async.commit_group;" ::: "memory")
#define CP_WAIT1()  asm volatile("cp.async.wait_group 1;" ::: "memory")

__device__ __forceinline__ void ldsm_x4(uint32_t& r0, uint32_t& r1, uint32_t& r2,
                                        uint32_t& r3, uint32_t addr) {
    asm volatile("ldmatrix.sync.aligned.m8n8.x4.shared.b16 {%0,%1,%2,%3}, [%4];"
                 : "=r"(r0), "=r"(r1), "=r"(r2), "=r"(r3) : "r"(addr));
}
__device__ __forceinline__ void mma16816(float c[4], uint32_t a0, uint32_t a1,
                                         uint32_t a2, uint32_t a3,
                                         uint32_t b0, uint32_t b1) {
    asm volatile(
        "mma.sync.aligned.m16n8k16.row.col.f32.f16.f16.f32 "
        "{%0,%1,%2,%3}, {%4,%5,%6,%7}, {%8,%9}, {%0,%1,%2,%3};"
        : "+f"(c[0]), "+f"(c[1]), "+f"(c[2]), "+f"(c[3])
        : "r"(a0), "r"(a1), "r"(a2), "r"(a3), "r"(b0), "r"(b1));
}

// =================================================================
// fp32 -> fp16 cast (vectorized: 4 floats -> 2 half2 per thread)
// =================================================================
__global__ void conv_cast(const float* __restrict__ src, __half* __restrict__ dst,
                          size_t total)
{
    size_t i = (size_t)blockIdx.x * blockDim.x + threadIdx.x;
    size_t e = i * 4;
    if (e >= total) return;
    float4 v = *(const float4*)(src + e);
    __half2 p0 = __floats2half2_rn(v.x, v.y);
    __half2 p1 = __floats2half2_rn(v.z, v.w);
    *(__half2*)(dst + e)     = p0;
    *(__half2*)(dst + e + 2) = p1;
}

// =================================================================
// mma.sync fp16 GEMM: C = A @ W^T + bias (fp32 accumulate).
// 128x128 CTA tile, 8 warps of 64x32, BK=64, 3-stage cp.async, ldmatrix.
// =================================================================
__global__ __launch_bounds__(256, 2) void gemm_mma(
    const __half* __restrict__ A, const __half* __restrict__ W,
    const float* __restrict__ bias, float* __restrict__ C, int Nout)
{
    extern __shared__ __half smg[];
    const int tid = threadIdx.x;
    const int wid = tid >> 5, lane = tid & 31;
    const int g = lane >> 2, tig = lane & 3;
    const int warp_m = wid >> 2, warp_n = wid & 3;     // 2 x 4 warps
    const int bc = blockIdx.x, br = blockIdx.y;

    const __half* gAb = A + (size_t)(br * BMg) * KK;
    const __half* gBb = W + (size_t)(bc * BNg) * KK;

    const uint32_t smb = smem_u32(smg);

    auto load_chunk = [&](int kc, int s) {
        const uint32_t smA = smb + (uint32_t)(s * 2 * STG_TILE) * 2;
        const uint32_t smB = smA + (uint32_t)STG_TILE * 2;
        const __half* gA = gAb + kc * BK;
        const __half* gB = gBb + kc * BK;
#pragma unroll
        for (int i = 0; i < 4; i++) {       // A: 128 rows x 8 x 16B
            int idx = i * 256 + tid;
            int r = idx >> 3, c16 = idx & 7;
            CP_ASYNC16(smA + r * (APITCH * 2) + c16 * 16, gA + (size_t)r * KK + c16 * 8);
        }
#pragma unroll
        for (int i = 0; i < 4; i++) {       // B: 128 rows x 8 x 16B
            int idx = i * 256 + tid;
            int r = idx >> 3, c16 = idx & 7;
            CP_ASYNC16(smB + r * (APITCH * 2) + c16 * 16, gB + (size_t)r * KK + c16 * 8);
        }
    };

    float acc[4][4][4];
#pragma unroll
    for (int mt = 0; mt < 4; mt++)
#pragma unroll
        for (int nt = 0; nt < 4; nt++)
#pragma unroll
            for (int q = 0; q < 4; q++) acc[mt][nt][q] = 0.f;

    // ldmatrix lane address components
    const int a_row = warp_m * 64 + (lane & 15);       // + mt*16
    const int a_kof = (lane >> 4) * 8;                 // + ks*16
    const int b_col = warp_n * 32 + (lane & 7) + ((lane >> 4) << 3);  // + ntp*16
    const int b_kof = ((lane >> 3) & 1) * 8;           // + ks*16

    load_chunk(0, 0); CP_COMMIT();
    load_chunk(1, 1); CP_COMMIT();

    for (int kc = 0; kc < NCH; kc++) {
        CP_WAIT1();            // chunk kc resident
        __syncthreads();
        if (kc + 2 < NCH) load_chunk(kc + 2, (kc + 2) % STAGES);
        CP_COMMIT();

        const int s = kc % STAGES;
        const uint32_t smA = smb + (uint32_t)(s * 2 * STG_TILE) * 2;
        const uint32_t smB = smA + (uint32_t)STG_TILE * 2;

#pragma unroll
        for (int ks = 0; ks < 4; ks++) {
            const int kb = ks * 16;
            uint32_t af[4][4], bf[2][4];
#pragma unroll
            for (int mt = 0; mt < 4; mt++) {
                uint32_t addr = smA + (uint32_t)(((a_row + mt * 16) * APITCH) + kb + a_kof) * 2;
                ldsm_x4(af[mt][0], af[mt][1], af[mt][2], af[mt][3], addr);
            }
#pragma unroll
            for (int ntp = 0; ntp < 2; ntp++) {
                uint32_t addr = smB + (uint32_t)(((b_col + ntp * 16) * APITCH) + kb + b_kof) * 2;
                ldsm_x4(bf[ntp][0], bf[ntp][1], bf[ntp][2], bf[ntp][3], addr);
            }
#pragma unroll
            for (int mt = 0; mt < 4; mt++)
#pragma unroll
                for (int ntp = 0; ntp < 2; ntp++) {
                    mma16816(acc[mt][2 * ntp],     af[mt][0], af[mt][1], af[mt][2], af[mt][3],
                             bf[ntp][0], bf[ntp][1]);
                    mma16816(acc[mt][2 * ntp + 1], af[mt][0], af[mt][1], af[mt][2], af[mt][3],
                             bf[ntp][2], bf[ntp][3]);
                }
        }
    }

    // ---- epilogue: direct register -> global with bias ----
#pragma unroll
    for (int mt = 0; mt < 4; mt++) {
        int row0 = br * BMg + warp_m * 64 + mt * 16 + g;
#pragma unroll
        for (int nt = 0; nt < 4; nt++) {
            int col = bc * BNg + warp_n * 32 + nt * 8 + 2 * tig;
            float b0 = bias[col], b1 = bias[col + 1];
            *(float2*)(C + (size_t)row0 * Nout + col) =
                make_float2(acc[mt][nt][0] + b0, acc[mt][nt][1] + b1);
            *(float2*)(C + (size_t)(row0 + 8) * Nout + col) =
                make_float2(acc[mt][nt][2] + b0, acc[mt][nt][3] + b1);
        }
    }
}

// =================================================================
// 64x64 smem matmul helper (validated)
// =================================================================
__device__ __forceinline__ void mm64(float* __restrict__ dst,
                                     const float* __restrict__ Am,
                                     const float* __restrict__ Bm,
                                     int tx, int ty, float dscale, float diagadd)
{
    float acc[4][4] = {};
#pragma unroll 8
    for (int k = 0; k < 64; k++) {
        float4 bv = *(const float4*)(Bm + k * LDm + 4 * tx);
        float a0 = Am[(4 * ty + 0) * LDm + k];
        float a1 = Am[(4 * ty + 1) * LDm + k];
        float a2 = Am[(4 * ty + 2) * LDm + k];
        float a3 = Am[(4 * ty + 3) * LDm + k];
        acc[0][0] += a0 * bv.x; acc[0][1] += a0 * bv.y; acc[0][2] += a0 * bv.z; acc[0][3] += a0 * bv.w;
        acc[1][0] += a1 * bv.x; acc[1][1] += a1 * bv.y; acc[1][2] += a1 * bv.z; acc[1][3] += a1 * bv.w;
        acc[2][0] += a2 * bv.x; acc[2][1] += a2 * bv.y; acc[2][2] += a2 * bv.z; acc[2][3] += a2 * bv.w;
        acc[3][0] += a3 * bv.x; acc[3][1] += a3 * bv.y; acc[3][2] += a3 * bv.z; acc[3][3] += a3 * bv.w;
    }
#pragma unroll
    for (int i = 0; i < 4; i++)
#pragma unroll
        for (int j = 0; j < 4; j++) {
            int r = 4 * ty + i, c = 4 * tx + j;
            dst[r * LDm + c] = acc[i][j] * dscale + ((r == c) ? diagadd : 0.f);
        }
    __syncthreads();
}

__device__ __forceinline__ void softmax_rows(float acc[4][4])
{
#pragma unroll
    for (int i = 0; i < 4; i++) {
        float m = fmaxf(fmaxf(acc[i][0], acc[i][1]), fmaxf(acc[i][2], acc[i][3]));
#pragma unroll
        for (int off = 8; off > 0; off >>= 1)
            m = fmaxf(m, __shfl_xor_sync(0xffffffffu, m, off, 16));
        float s = 0.f;
#pragma unroll
        for (int j = 0; j < 4; j++) { acc[i][j] = __expf(acc[i][j] - m); s += acc[i][j]; }
#pragma unroll
        for (int off = 8; off > 0; off >>= 1)
            s += __shfl_xor_sync(0xffffffffu, s, off, 16);
        float inv = 1.f / s;
#pragma unroll
        for (int j = 0; j < 4; j++) acc[i][j] *= inv;
    }
}

// write a 4-wide fp16 output row segment into g_abuf
__device__ __forceinline__ void store_out_fp16(size_t row, int col, const float o[4])
{
    __half* dst = g_abuf + row * KK + col;
    *(__half2*)(dst)     = __floats2half2_rn(o[0], o[1]);
    *(__half2*)(dst + 2) = __floats2half2_rn(o[2], o[3]);
}

// =================================================================
// Temporal attention: writes fp16 directly into g_abuf (FC GEMM input)
// =================================================================
__global__ __launch_bounds__(256, 2) void temporal_attn()
{
    extern __shared__ float smT[];
    float* Q  = smT;
    float* Kt = Q  + 64 * LDm;
    float* V  = Kt + 64 * LDm;
    float* P  = V  + 64 * LDm;
    const int tid = threadIdx.x, tx = tid & 15, ty = tid >> 4;
    const int h = blockIdx.x & 3;
    const int c = (blockIdx.x >> 2) & 63;
    const int b = blockIdx.x >> 8;

    const float* qk = g_qkv + (size_t)b * Ll * M3 + h * 64;
#pragma unroll
    for (int it = 0; it < 16; it++) {
        int idx = it * 256 + tid;
        int nn = idx >> 6, e = idx & 63;
        const float* p = qk + (size_t)(nn * Cc + c) * M3 + e;
        Q [nn * LDm + e]  = p[0];
        Kt[e  * LDm + nn] = p[Dd];
        V [nn * LDm + e]  = p[2 * Dd];
    }
    __syncthreads();

    float acc[4][4] = {};
#pragma unroll 8
    for (int k = 0; k < 64; k++) {
        float4 bv = *(const float4*)(Kt + k * LDm + 4 * tx);
        float a0 = Q[(4 * ty + 0) * LDm + k];
        float a1 = Q[(4 * ty + 1) * LDm + k];
        float a2 = Q[(4 * ty + 2) * LDm + k];
        float a3 = Q[(4 * ty + 3) * LDm + k];
        acc[0][0] += a0 * bv.x; acc[0][1] += a0 * bv.y; acc[0][2] += a0 * bv.z; acc[0][3] += a0 * bv.w;
        acc[1][0] += a1 * bv.x; acc[1][1] += a1 * bv.y; acc[1][2] += a1 * bv.z; acc[1][3] += a1 * bv.w;
        acc[2][0] += a2 * bv.x; acc[2][1] += a2 * bv.y; acc[2][2] += a2 * bv.z; acc[2][3] += a2 * bv.w;
        acc[3][0] += a3 * bv.x; acc[3][1] += a3 * bv.y; acc[3][2] += a3 * bv.z; acc[3][3] += a3 * bv.w;
    }
#pragma unroll
    for (int i = 0; i < 4; i++)
#pragma unroll
        for (int j = 0; j < 4; j++) acc[i][j] *= SCALE_ATT;

    softmax_rows(acc);

#pragma unroll
    for (int i = 0; i < 4; i++)
#pragma unroll
        for (int j = 0; j < 4; j++)
            P[(4 * ty + i) * LDm + 4 * tx + j] = acc[i][j];
    __syncthreads();

    float o[4][4] = {};
#pragma unroll 8
    for (int k = 0; k < 64; k++) {
        float4 bv = *(const float4*)(V + k * LDm + 4 * tx);
        float a0 = P[(4 * ty + 0) * LDm + k];
        float a1 = P[(4 * ty + 1) * LDm + k];
        float a2 = P[(4 * ty + 2) * LDm + k];
        float a3 = P[(4 * ty + 3) * LDm + k];
        o[0][0] += a0 * bv.x; o[0][1] += a0 * bv.y; o[0][2] += a0 * bv.z; o[0][3] += a0 * bv.w;
        o[1][0] += a1 * bv.x; o[1][1] += a1 * bv.y; o[1][2] += a1 * bv.z; o[1][3] += a1 * bv.w;
        o[2][0] += a2 * bv.x; o[2][1] += a2 * bv.y; o[2][2] += a2 * bv.z; o[2][3] += a2 * bv.w;
        o[3][0] += a3 * bv.x; o[3][1] += a3 * bv.y; o[3][2] += a3 * bv.z; o[3][3] += a3 * bv.w;
    }
#pragma unroll
    for (int i = 0; i < 4; i++) {
        size_t l = (size_t)(4 * ty + i) * Cc + c;
        store_out_fp16((size_t)b * Ll + l, h * 64 + 4 * tx, o[i]);
    }
}

// =================================================================
// Spatial branch: NS 5 iters, Gregory 6 terms; fp16 output to g_abuf
// =================================================================
__global__ __launch_bounds__(256, 2) void spatial_riemann(
    const float* __restrict__ x, const float* __restrict__ head_scales)
{
    extern __shared__ float smS[];
    float* B0 = smS;
    float* B1 = B0 + 64 * LDm;
    float* B2 = B1 + 64 * LDm;
    float* B3 = B2 + 64 * LDm;
    float* LM = B3 + 64 * LDm;
    float* red = LM + 64 * LDm;
    __shared__ float s_alpha;

    const int tid = threadIdx.x, tx = tid & 15, ty = tid >> 4;
    const int n = blockIdx.x & 63, b = blockIdx.x >> 6;
    const float* xb = x + ((size_t)b * Ll + n * Cc) * Dd;

    float sacc[4][4] = {};
    for (int kc = 0; kc < 8; kc++) {
#pragma unroll
        for (int it = 0; it < 16; it++) {
            int idx = it * 256 + tid;
            int r = idx >> 6, col = idx & 63;
            float v = xb[(size_t)r * Dd + kc * 64 + col];
            B2[r * LDm + col] = v;
            B3[col * LDm + r] = v;
        }
        __syncthreads();
#pragma unroll 8
        for (int k = 0; k < 64; k++) {
            float4 bv = *(const float4*)(B3 + k * LDm + 4 * tx);
            float a0 = B2[(4 * ty + 0) * LDm + k];
            float a1 = B2[(4 * ty + 1) * LDm + k];
            float a2 = B2[(4 * ty + 2) * LDm + k];
            float a3 = B2[(4 * ty + 3) * LDm + k];
            sacc[0][0] += a0 * bv.x; sacc[0][1] += a0 * bv.y; sacc[0][2] += a0 * bv.z; sacc[0][3] += a0 * bv.w;
            sacc[1][0] += a1 * bv.x; sacc[1][1] += a1 * bv.y; sacc[1][2] += a1 * bv.z; sacc[1][3] += a1 * bv.w;
            sacc[2][0] += a2 * bv.x; sacc[2][1] += a2 * bv.y; sacc[2][2] += a2 * bv.z; sacc[2][3] += a2 * bv.w;
            sacc[3][0] += a3 * bv.x; sacc[3][1] += a3 * bv.y; sacc[3][2] += a3 * bv.z; sacc[3][3] += a3 * bv.w;
        }
        __syncthreads();
    }
#pragma unroll
    for (int i = 0; i < 4; i++)
#pragma unroll
        for (int j = 0; j < 4; j++) {
            int r = 4 * ty + i, c = 4 * tx + j;
            float v = sacc[i][j] * (1.f / (float)Dd);
            if (r == c) v += 1.f + SPD_EPSF;
            B0[r * LDm + c] = v;
        }
    __syncthreads();

    {
        int r = tid >> 2, seg = tid & 3;
        float s = 0.f;
#pragma unroll
        for (int j = 0; j < 16; j++) s += fabsf(B0[r * LDm + seg * 16 + j]);
        red[tid] = s;
    }
    __syncthreads();
    if (tid == 0) {
        float rmax = 0.f;
        for (int r = 0; r < 64; r++)
            rmax = fmaxf(rmax, red[4 * r] + red[4 * r + 1] + red[4 * r + 2] + red[4 * r + 3]);
        s_alpha = 2.f / (1.f + rmax);
    }
    __syncthreads();
    float alpha = s_alpha;

#pragma unroll
    for (int i = 0; i < 4; i++)
#pragma unroll
        for (int j = 0; j < 4; j++) {
            int r = 4 * ty + i, c = 4 * tx + j;
            B1[r * LDm + c] = (r == c) ? alpha : 0.f;
        }
    __syncthreads();

    for (int it = 0; it < 5; it++) {
        mm64(B2, B0, B1, tx, ty, 1.f, 0.f);
        mm64(B3, B1, B2, tx, ty, 1.f, 0.f);
#pragma unroll
        for (int i = 0; i < 4; i++)
#pragma unroll
            for (int j = 0; j < 4; j++) {
                int r = 4 * ty + i, c = 4 * tx + j;
                B1[r * LDm + c] = 2.f * B1[r * LDm + c] - B3[r * LDm + c];
            }
        __syncthreads();
    }

#pragma unroll
    for (int i = 0; i < 4; i++)
#pragma unroll
        for (int j = 0; j < 4; j++) {
            int r = 4 * ty + i, c = 4 * tx + j;
            B2[r * LDm + c] = ((r == c) ? 1.f : 0.f) - 2.f * B1[r * LDm + c];
        }
    __syncthreads();

    mm64(B0, B2, B2, tx, ty, 1.f, 0.f);   // W = Z^2

#pragma unroll
    for (int i = 0; i < 4; i++)
#pragma unroll
        for (int j = 0; j < 4; j++) {
            int r = 4 * ty + i, c = 4 * tx + j;
            B3[r * LDm + c] = (r == c) ? (1.f / 11.f) : 0.f;
        }
    __syncthreads();
    {
        float* cur = B3; float* oth = B1;
        for (int m = 4; m >= 0; m--) {
            mm64(oth, cur, B0, tx, ty, 1.f, 1.f / (float)(2 * m + 1));
            float* t = cur; cur = oth; oth = t;
        }
        mm64(LM, B2, cur, tx, ty, 2.f, 0.f);   // Lm = 2 Z P
    }

    const float* qk = g_qkv + (size_t)b * Ll * M3 + H2d * 64;
    for (int h = 0; h < H2d; h++) {
        float hs = head_scales[h];
#pragma unroll
        for (int it = 0; it < 16; it++) {
            int idx = it * 256 + tid;
            int r = idx >> 6, e = idx & 63;
            const float* p = qk + (size_t)(n * Cc + r) * M3 + h * 64 + e;
            B0[r * LDm + e] = p[0];
            B2[e * LDm + r] = p[Dd];
            B3[r * LDm + e] = p[2 * Dd];
        }
        __syncthreads();

        float a4[4][4] = {};
#pragma unroll 8
        for (int k = 0; k < 64; k++) {
            float4 bv = *(const float4*)(B2 + k * LDm + 4 * tx);
            float a0 = B0[(4 * ty + 0) * LDm + k];
            float a1 = B0[(4 * ty + 1) * LDm + k];
            float a2 = B0[(4 * ty + 2) * LDm + k];
            float a3 = B0[(4 * ty + 3) * LDm + k];
            a4[0][0] += a0 * bv.x; a4[0][1] += a0 * bv.y; a4[0][2] += a0 * bv.z; a4[0][3] += a0 * bv.w;
            a4[1][0] += a1 * bv.x; a4[1][1] += a1 * bv.y; a4[1][2] += a1 * bv.z; a4[1][3] += a1 * bv.w;
            a4[2][0] += a2 * bv.x; a4[2][1] += a2 * bv.y; a4[2][2] += a2 * bv.z; a4[2][3] += a2 * bv.w;
            a4[3][0] += a3 * bv.x; a4[3][1] += a3 * bv.y; a4[3][2] += a3 * bv.z; a4[3][3] += a3 * bv.w;
        }
#pragma unroll
        for (int i = 0; i < 4; i++)
#pragma unroll
            for (int j = 0; j < 4; j++)
                a4[i][j] = a4[i][j] * SCALE_ATT + hs * LM[(4 * ty + i) * LDm + 4 * tx + j];

        softmax_rows(a4);

#pragma unroll
        for (int i = 0; i < 4; i++)
#pragma unroll
            for (int j = 0; j < 4; j++)
                B1[(4 * ty + i) * LDm + 4 * tx + j] = a4[i][j];
        __syncthreads();

        float o[4][4] = {};
#pragma unroll 8
        for (int k = 0; k < 64; k++) {
            float4 bv = *(const float4*)(B3 + k * LDm + 4 * tx);
            float a0 = B1[(4 * ty + 0) * LDm + k];
            float a1 = B1[(4 * ty + 1) * LDm + k];
            float a2 = B1[(4 * ty + 2) * LDm + k];
            float a3 = B1[(4 * ty + 3) * LDm + k];
            o[0][0] += a0 * bv.x; o[0][1] += a0 * bv.y; o[0][2] += a0 * bv.z; o[0][3] += a0 * bv.w;
            o[1][0] += a1 * bv.x; o[1][1] += a1 * bv.y; o[1][2] += a1 * bv.z; o[1][3] += a1 * bv.w;
            o[2][0] += a2 * bv.x; o[2][1] += a2 * bv.y; o[2][2] += a2 * bv.z; o[2][3] += a2 * bv.w;
            o[3][0] += a3 * bv.x; o[3][1] += a3 * bv.y; o[3][2] += a3 * bv.z; o[3][3] += a3 * bv.w;
        }
#pragma unroll
        for (int i = 0; i < 4; i++) {
            size_t l = (size_t)n * Cc + 4 * ty + i;
            store_out_fp16((size_t)b * Ll + l, (H2d + h) * 64 + 4 * tx, o[i]);
        }
        __syncthreads();
    }
}

// =================================================================
// launch
// =================================================================
extern "C" void kernel_launch(void* const* d_in, const int* in_sizes, int n_in,
                              void* d_out, int out_size)
{
    const float* x     = (const float*)d_in[0];
    const float* qkv_w = (const float*)d_in[1];
    const float* qkv_b = (const float*)d_in[2];
    const float* fc_w  = (const float*)d_in[3];
    const float* fc_b  = (const float*)d_in[4];
    const float* hsc   = (const float*)d_in[5];
    float* out = (float*)d_out;

    float* p_qkv = nullptr;
    __half* p_abuf = nullptr;
    __half* p_wbuf = nullptr;
    cudaGetSymbolAddress((void**)&p_qkv, g_qkv);
    cudaGetSymbolAddress((void**)&p_abuf, g_abuf);
    cudaGetSymbolAddress((void**)&p_wbuf, g_wbuf);

    const int smemT = 4 * 64 * LDm * (int)sizeof(float);
    const int smemS = 5 * 64 * LDm * (int)sizeof(float) + 256 * 4;
    const int smemG = STAGES * 2 * STG_TILE * (int)sizeof(__half);   // 110592
    cudaFuncSetAttribute(temporal_attn, cudaFuncAttributeMaxDynamicSharedMemorySize, smemT);
    cudaFuncSetAttribute(spatial_riemann, cudaFuncAttributeMaxDynamicSharedMemorySize, smemS);
    cudaFuncSetAttribute(gemm_mma, cudaFuncAttributeMaxDynamicSharedMemorySize, smemG);

    // 1) cast x and qkv_w to fp16
    {
        size_t tot = (size_t)MROWS * Dd;
        conv_cast<<<(unsigned)(tot / 1024), 256>>>(x, p_abuf, tot);
        size_t totw = (size_t)M3 * Dd;
        conv_cast<<<(unsigned)(totw / 1024), 256>>>(qkv_w, p_wbuf, totw);
    }
    // 2) QKV projection via mma.sync fp16
    {
        dim3 grid(M3 / BNg, MROWS / BMg);   // (12, 512)
        gemm_mma<<<grid, 256, smemG>>>(p_abuf, p_wbuf, qkv_b, p_qkv, M3);
    }
    // 3) temporal heads (write fp16 into g_abuf)
    temporal_attn<<<Bsz * Cc * H2d, 256, smemT>>>();
    // 4) SPD log bias + spatial heads (write fp16 into g_abuf)
    spatial_riemann<<<Bsz * Nn, 256, smemS>>>(x, hsc);
    // 5) cast fc_w to fp16
    {
        size_t totw = (size_t)Dd * Dd;
        conv_cast<<<(unsigned)(totw / 1024), 256>>>(fc_w, p_wbuf, totw);
    }
    // 6) output projection via mma.sync fp16
    {
        dim3 grid(Dd / BNg, MROWS / BMg);   // (4, 512)
        gemm_mma<<<grid, 256, smemG>>>(p_abuf, p_wbuf, fc_b, out, Dd);
    }
}